// round 11
// baseline (speedup 1.0000x reference)
#include <cuda_runtime.h>
#include <cstdint>
#include <algorithm>

// Problem constants
#define NROWS   16          // only b=0 rows matter for the output
#define CTOT    384
#define NG      16          // channel groups
#define CPG     24          // channels per group (384/16)
#define HW      1024        // 32*32
#define KSEL    20
#define PTOT    96
#define NREM    76          // P - K
#define NUNSEL  1004        // 1024 - 20

struct SlotTab { short s[NUNSEL]; };   // unselected-rank -> output slot (-1 = drop)

// per-group score partials: [group][row][pixel] (1 MB, every slot written once)
__device__ float g_partial[NG][NROWS][HW];

// ---------------------------------------------------------------------------
// Kernel 1: tap-decomposed fused dw3x3*pw1x1 partial score (R7 structure,
// channel loop unrolled x8 for deeper load MLP)
// ---------------------------------------------------------------------------
__global__ void __launch_bounds__(256) conv_kernel(
    const float* __restrict__ feat,
    const float* __restrict__ dw_w,
    const float* __restrict__ pw_w)
{
    const int grp = blockIdx.x;     // 0..15
    const int row = blockIdx.y;     // 0..15
    const int t   = threadIdx.x;    // 0..255
    const int p0  = t * 4;
    const int x4  = p0 & 31;
    const int y   = p0 >> 5;

    __shared__ float P[9][34 * 34];              // zero-padded tap planes (41.6 KB)
    __shared__ unsigned long long wp[CPG][9];    // packed (w,w) fused weights

    for (int i = t; i < 9 * 34 * 34; i += 256) (&P[0][0])[i] = 0.f;
    for (int i = t; i < CPG * 9; i += 256) {
        int ci = i / 9, k = i % 9, c = grp * CPG + ci;
        float w = pw_w[c] * dw_w[c * 9 + k];
        unsigned int u = __float_as_uint(w);
        wp[ci][k] = ((unsigned long long)u << 32) | (unsigned long long)u;
    }
    __syncthreads();

    const ulonglong2* base = reinterpret_cast<const ulonglong2*>(
        feat + ((size_t)row * CTOT + (size_t)grp * CPG) * HW) + t;

    unsigned long long accA[9], accB[9];
    #pragma unroll
    for (int k = 0; k < 9; ++k) { accA[k] = 0ull; accB[k] = 0ull; }

    #pragma unroll 8
    for (int c = 0; c < CPG; ++c) {
        ulonglong2 f = base[c * 256];            // 4 pixels (2x f32x2)
        #pragma unroll
        for (int k = 0; k < 9; ++k) {
            unsigned long long w = wp[c][k];
            asm("fma.rn.f32x2 %0, %1, %2, %0;" : "+l"(accA[k]) : "l"(f.x), "l"(w));
            asm("fma.rn.f32x2 %0, %1, %2, %0;" : "+l"(accB[k]) : "l"(f.y), "l"(w));
        }
    }

    // write tap planes (interior of padded 34x34)
    #pragma unroll
    for (int k = 0; k < 9; ++k) {
        float* pr = &P[k][(y + 1) * 34 + (x4 + 1)];
        pr[0] = __uint_as_float((unsigned int)(accA[k]));
        pr[1] = __uint_as_float((unsigned int)(accA[k] >> 32));
        pr[2] = __uint_as_float((unsigned int)(accB[k]));
        pr[3] = __uint_as_float((unsigned int)(accB[k] >> 32));
    }
    __syncthreads();

    // 9-tap gather: score(y,x) = sum_{ky,kx} P[ky*3+kx][(y+ky)*34 + (x+kx)]
    float s0 = 0.f, s1 = 0.f, s2 = 0.f, s3 = 0.f;
    #pragma unroll
    for (int ky = 0; ky < 3; ++ky)
        #pragma unroll
        for (int kx = 0; kx < 3; ++kx) {
            const float* pr = &P[ky * 3 + kx][(y + ky) * 34 + x4 + kx];
            s0 += pr[0]; s1 += pr[1]; s2 += pr[2]; s3 += pr[3];
        }

    __stcg(reinterpret_cast<float4*>(&g_partial[grp][row][p0]),
           make_float4(s0, s1, s2, s3));
}

// ---------------------------------------------------------------------------
// Kernel 2: per-row two-level radix top-20, latency-lean (256 thr, ~7 barriers)
// out layout: x_out[16][96] then y_out[16][96], FLOAT32
// ---------------------------------------------------------------------------
// find max bucket T with suffix count >= need; also count strictly above T.
// warp0 only; all lanes return identical T / cntAbove.
__device__ __forceinline__ void find_thresh(const unsigned int* hist, int need, int lane,
                                            int& T, int& cntAbove)
{
    const int base = lane * 8;
    unsigned int h[8], ls[8];
    #pragma unroll
    for (int j = 0; j < 8; ++j) h[j] = hist[base + j];
    ls[7] = h[7];
    #pragma unroll
    for (int j = 6; j >= 0; --j) ls[j] = ls[j + 1] + h[j];
    unsigned int tot = ls[0], s = tot;
    #pragma unroll
    for (int off = 1; off < 32; off <<= 1) {
        unsigned int o = __shfl_down_sync(0xffffffffu, s, off);
        if (lane + off < 32) s += o;
    }
    unsigned int hi = s - tot;          // totals of lanes strictly above this lane
    int best = -1;
    #pragma unroll
    for (int j = 7; j >= 0; --j)
        if (best < 0 && hi + ls[j] >= (unsigned int)need) best = base + j;
    #pragma unroll
    for (int off = 16; off; off >>= 1)
        best = max(best, __shfl_down_sync(0xffffffffu, best, off));
    best = __shfl_sync(0xffffffffu, best, 0);
    T = best;
    unsigned int c = 0;
    if (base > T)          c = tot;
    else if (base + 7 > T) c = ls[T - base + 1];
    #pragma unroll
    for (int off = 16; off; off >>= 1)
        c += __shfl_xor_sync(0xffffffffu, c, off);
    cntAbove = (int)c;
}

__global__ void __launch_bounds__(256) topk_kernel(float* __restrict__ out, SlotTab tab)
{
    const int row = blockIdx.x;   // 0..15
    const int t   = threadIdx.x;  // 0..255
    const int lane = t & 31;
    const int p0  = t * 4;

    __shared__ unsigned int        hist1[256];
    __shared__ unsigned int        hist2[256];
    __shared__ unsigned long long  candkey[256];
    __shared__ int                 sel20[KSEL];
    __shared__ unsigned int        ccnt;
    __shared__ int                 sT1, sT2, sneed2;

    // issue the 16 independent partial-sum loads first (latency covered by init)
    float4 acc4 = make_float4(0.f, 0.f, 0.f, 0.f);
    #pragma unroll
    for (int g = 0; g < NG; ++g) {
        float4 f = __ldcg(reinterpret_cast<const float4*>(&g_partial[g][row][p0]));
        acc4.x += f.x; acc4.y += f.y; acc4.z += f.z; acc4.w += f.w;
    }

    hist1[t] = 0u;
    hist2[t] = 0u;
    if (t == 0) ccnt = 0u;

    float v[4] = { acc4.x, acc4.y, acc4.z, acc4.w };
    unsigned int ordv[4];
    unsigned long long keyv[4];
    #pragma unroll
    for (int j = 0; j < 4; ++j) {
        unsigned int bits = __float_as_uint(v[j]);
        ordv[j] = (bits & 0x80000000u) ? ~bits : (bits | 0x80000000u);
        keyv[j] = ((unsigned long long)ordv[j] << 32) | (unsigned int)(1023 - (p0 + j));
    }
    __syncthreads();

    #pragma unroll
    for (int j = 0; j < 4; ++j) atomicAdd(&hist1[ordv[j] >> 24], 1u);
    __syncthreads();

    if (t < 32) {
        int T1, cA;
        find_thresh(hist1, KSEL, lane, T1, cA);
        if (lane == 0) { sT1 = T1; sneed2 = KSEL - cA; }
    }
    __syncthreads();

    const int T1 = sT1;
    #pragma unroll
    for (int j = 0; j < 4; ++j)
        if ((int)(ordv[j] >> 24) == T1)
            atomicAdd(&hist2[(ordv[j] >> 16) & 0xFFu], 1u);
    __syncthreads();

    if (t < 32) {
        int T2, cA2;
        find_thresh(hist2, sneed2, lane, T2, cA2);
        if (lane == 0) sT2 = T2;
    }
    __syncthreads();

    const int T2 = sT2;
    #pragma unroll
    for (int j = 0; j < 4; ++j) {
        int b1 = (int)(ordv[j] >> 24);
        bool cand = (b1 > T1) || (b1 == T1 && (int)((ordv[j] >> 16) & 0xFFu) >= T2);
        if (cand) {
            unsigned int pos = atomicAdd(&ccnt, 1u);
            candkey[pos & 255u] = keyv[j];   // nc << 256 by construction
        }
    }
    __syncthreads();

    // exact rank among candidates == exact global rank (desc value, asc index)
    const int nc = (int)ccnt;
    if (t < nc) {
        unsigned long long my = candkey[t];
        int rank = 0;
        for (int j = 0; j < nc; ++j) rank += (candkey[j] > my);
        if (rank < KSEL) {
            int idx = 1023 - (int)(my & 0xFFFFFFFFu);
            sel20[rank] = idx;
            int xc = idx & 31, yc = idx >> 5;
            xc = max(xc, 1); yc = max(yc, 1);
            out[row * PTOT + rank] = (float)xc;
            out[NROWS * PTOT + row * PTOT + rank] = (float)yc;
        }
    }
    __syncthreads();

    // unselected rank directly: rank(p) = p - #{selected idx < p}
    #pragma unroll
    for (int j = 0; j < 4; ++j) {
        int p = p0 + j;
        int cntLess = 0, isSel = 0;
        #pragma unroll
        for (int i = 0; i < KSEL; ++i) {
            int d = p - sel20[i];
            cntLess += (d > 0);
            isSel   |= (d == 0);
        }
        if (!isSel) {
            int s = tab.s[p - cntLess];
            if (s >= 0) {
                int xc = p & 31, yc = p >> 5;
                xc = max(xc, 1); yc = max(yc, 1);
                out[row * PTOT + KSEL + s] = (float)xc;
                out[NROWS * PTOT + row * PTOT + KSEL + s] = (float)yc;
            }
        }
    }
}

// ---------------------------------------------------------------------------
// Host: replicate jax.random.permutation(jax.random.key(42), 1004)[:76]
// (threefry2x32, partitionable: foldlike split + xor random_bits)
// ---------------------------------------------------------------------------
static inline uint32_t rotl32(uint32_t v, int d) { return (v << d) | (v >> (32 - d)); }

static void threefry2x32_host(uint32_t k0, uint32_t k1, uint32_t c0, uint32_t c1,
                              uint32_t* o0, uint32_t* o1)
{
    uint32_t ks[3] = { k0, k1, k0 ^ k1 ^ 0x1BD11BDAu };
    static const int rot[2][4] = { {13, 15, 26, 6}, {17, 29, 16, 24} };
    uint32_t x0 = c0 + ks[0], x1 = c1 + ks[1];
    for (int g = 0; g < 5; ++g) {
        const int* rr = rot[g & 1];
        for (int i = 0; i < 4; ++i) {
            x0 += x1; x1 = rotl32(x1, rr[i]); x1 ^= x0;
        }
        x0 += ks[(g + 1) % 3];
        x1 += ks[(g + 2) % 3] + (uint32_t)(g + 1);
    }
    *o0 = x0; *o1 = x1;
}

static void compute_slot_table(SlotTab* tab)
{
    uint32_t s0, s1;
    threefry2x32_host(0u, 42u, 0u, 1u, &s0, &s1);   // foldlike split of key(42)

    static uint32_t keys[NUNSEL];
    static int idx[NUNSEL];
    for (int i = 0; i < NUNSEL; ++i) {
        uint32_t o0, o1;
        threefry2x32_host(s0, s1, 0u, (uint32_t)i, &o0, &o1);
        keys[i] = o0 ^ o1;                           // partitionable random_bits
        idx[i] = i;
    }
    std::stable_sort(idx, idx + NUNSEL,
                     [](int a, int b) { return keys[a] < keys[b]; });
    for (int i = 0; i < NUNSEL; ++i) tab->s[i] = -1;
    for (int j = 0; j < NREM; ++j) tab->s[idx[j]] = (short)j;
}

extern "C" void kernel_launch(void* const* d_in, const int* in_sizes, int n_in,
                              void* d_out, int out_size)
{
    const float* feat = (const float*)d_in[0];   // (8,16,384,32,32)
    const float* dw_w = (const float*)d_in[1];   // (384,1,3,3)
    // d_in[2] = dw_b (constant shift, irrelevant to ranking)
    const float* pw_w = (const float*)d_in[3];   // (1,384,1,1)
    // d_in[4] = pw_b (constant shift, irrelevant)

    SlotTab tab;
    compute_slot_table(&tab);   // deterministic, host-side, capture-time only

    dim3 grid(NG, NROWS);
    conv_kernel<<<grid, 256>>>(feat, dw_w, pw_w);
    topk_kernel<<<NROWS, 256>>>((float*)d_out, tab);
}

// round 12
// speedup vs baseline: 1.0821x; 1.0821x over previous
#include <cuda_runtime.h>
#include <cstdint>
#include <algorithm>

// Problem constants
#define NROWS   16          // only b=0 rows matter for the output
#define CTOT    384
#define NG      16          // channel groups
#define CPG     24          // channels per group (384/16)
#define HW      1024        // 32*32
#define KSEL    20
#define PTOT    96
#define NREM    76          // P - K
#define NUNSEL  1004        // 1024 - 20

struct Perm76 { int v[NREM]; };

// per-group score partials: [group][row][pixel] (1 MB, every slot written once)
__device__ float g_partial[NG][NROWS][HW];

// ---------------------------------------------------------------------------
// Kernel 1: tap-decomposed fused dw3x3*pw1x1 partial score (R11 proven: x8 MLP)
// ---------------------------------------------------------------------------
__global__ void __launch_bounds__(256) conv_kernel(
    const float* __restrict__ feat,
    const float* __restrict__ dw_w,
    const float* __restrict__ pw_w)
{
    const int grp = blockIdx.x;     // 0..15
    const int row = blockIdx.y;     // 0..15
    const int t   = threadIdx.x;    // 0..255
    const int p0  = t * 4;
    const int x4  = p0 & 31;
    const int y   = p0 >> 5;

    __shared__ float P[9][34 * 34];              // zero-padded tap planes (41.6 KB)
    __shared__ unsigned long long wp[CPG][9];    // packed (w,w) fused weights

    for (int i = t; i < 9 * 34 * 34; i += 256) (&P[0][0])[i] = 0.f;
    for (int i = t; i < CPG * 9; i += 256) {
        int ci = i / 9, k = i % 9, c = grp * CPG + ci;
        float w = pw_w[c] * dw_w[c * 9 + k];
        unsigned int u = __float_as_uint(w);
        wp[ci][k] = ((unsigned long long)u << 32) | (unsigned long long)u;
    }
    __syncthreads();

    const ulonglong2* base = reinterpret_cast<const ulonglong2*>(
        feat + ((size_t)row * CTOT + (size_t)grp * CPG) * HW) + t;

    unsigned long long accA[9], accB[9];
    #pragma unroll
    for (int k = 0; k < 9; ++k) { accA[k] = 0ull; accB[k] = 0ull; }

    #pragma unroll 8
    for (int c = 0; c < CPG; ++c) {
        ulonglong2 f = base[c * 256];            // 4 pixels (2x f32x2)
        #pragma unroll
        for (int k = 0; k < 9; ++k) {
            unsigned long long w = wp[c][k];
            asm("fma.rn.f32x2 %0, %1, %2, %0;" : "+l"(accA[k]) : "l"(f.x), "l"(w));
            asm("fma.rn.f32x2 %0, %1, %2, %0;" : "+l"(accB[k]) : "l"(f.y), "l"(w));
        }
    }

    // write tap planes (interior of padded 34x34)
    #pragma unroll
    for (int k = 0; k < 9; ++k) {
        float* pr = &P[k][(y + 1) * 34 + (x4 + 1)];
        pr[0] = __uint_as_float((unsigned int)(accA[k]));
        pr[1] = __uint_as_float((unsigned int)(accA[k] >> 32));
        pr[2] = __uint_as_float((unsigned int)(accB[k]));
        pr[3] = __uint_as_float((unsigned int)(accB[k] >> 32));
    }
    __syncthreads();

    // 9-tap gather: score(y,x) = sum_{ky,kx} P[ky*3+kx][(y+ky)*34 + (x+kx)]
    float s0 = 0.f, s1 = 0.f, s2 = 0.f, s3 = 0.f;
    #pragma unroll
    for (int ky = 0; ky < 3; ++ky)
        #pragma unroll
        for (int kx = 0; kx < 3; ++kx) {
            const float* pr = &P[ky * 3 + kx][(y + ky) * 34 + x4 + kx];
            s0 += pr[0]; s1 += pr[1]; s2 += pr[2]; s3 += pr[3];
        }

    __stcg(reinterpret_cast<float4*>(&g_partial[grp][row][p0]),
           make_float4(s0, s1, s2, s3));
}

// ---------------------------------------------------------------------------
// Kernel 2: per-row two-level radix top-20 (R7 1024-thread structure, plus
// warp-aggregated histogram atomics)
// out layout: x_out[16][96] then y_out[16][96], FLOAT32
// ---------------------------------------------------------------------------
// find max bucket T with suffix count >= need; also count strictly above T.
// warp0 only; all lanes return identical T / cntAbove.
__device__ __forceinline__ void find_thresh(const unsigned int* hist, int need, int lane,
                                            int& T, int& cntAbove)
{
    const int base = lane * 8;
    unsigned int h[8], ls[8];
    #pragma unroll
    for (int j = 0; j < 8; ++j) h[j] = hist[base + j];
    ls[7] = h[7];
    #pragma unroll
    for (int j = 6; j >= 0; --j) ls[j] = ls[j + 1] + h[j];
    unsigned int tot = ls[0], s = tot;
    #pragma unroll
    for (int off = 1; off < 32; off <<= 1) {
        unsigned int o = __shfl_down_sync(0xffffffffu, s, off);
        if (lane + off < 32) s += o;
    }
    unsigned int hi = s - tot;          // totals of lanes strictly above this lane
    int best = -1;
    #pragma unroll
    for (int j = 7; j >= 0; --j)
        if (best < 0 && hi + ls[j] >= (unsigned int)need) best = base + j;
    #pragma unroll
    for (int off = 16; off; off >>= 1)
        best = max(best, __shfl_down_sync(0xffffffffu, best, off));
    best = __shfl_sync(0xffffffffu, best, 0);
    T = best;
    unsigned int c = 0;
    if (base > T)          c = tot;
    else if (base + 7 > T) c = ls[T - base + 1];
    #pragma unroll
    for (int off = 16; off; off >>= 1)
        c += __shfl_xor_sync(0xffffffffu, c, off);
    cntAbove = (int)c;
}

// warp-aggregated histogram add: one atomic per unique bucket per warp.
// 'valid' lanes contribute; invalid lanes use a unique dummy key and skip.
__device__ __forceinline__ void hist_add(unsigned int* hist, int bucket,
                                         bool valid, int lane)
{
    int key = valid ? bucket : (512 + lane);            // dummies are unique
    unsigned int mask = __match_any_sync(0xffffffffu, key);
    int leader = __ffs(mask) - 1;
    if (valid && lane == leader)
        atomicAdd(&hist[bucket], (unsigned int)__popc(mask));
}

__global__ void __launch_bounds__(1024) topk_kernel(float* __restrict__ out, Perm76 perm)
{
    const int r = blockIdx.x;     // 0..15
    const int t = threadIdx.x;    // 0..1023 == pixel index
    const int lane = t & 31, wrp = t >> 5;

    __shared__ unsigned int        hist1[256];
    __shared__ unsigned int        hist2[256];
    __shared__ unsigned long long  candkey[256];
    __shared__ unsigned char       selflag[1024];
    __shared__ short               slot_of_rank[NUNSEL];
    __shared__ int                 wtot[32];
    __shared__ unsigned int        ccnt;
    __shared__ int                 sT1, sT2, sneed2;

    // issue the 16 independent partial-sum loads immediately (latency covered)
    float v = 0.f;
    #pragma unroll
    for (int g = 0; g < NG; ++g) v += __ldcg(&g_partial[g][r][t]);

    if (t < 256) { hist1[t] = 0u; hist2[t] = 0u; }
    selflag[t] = 0;
    if (t == 0) ccnt = 0u;
    for (int i = t; i < NUNSEL; i += 1024) slot_of_rank[i] = -1;
    __syncthreads();
    if (t < NREM) slot_of_rank[perm.v[t]] = (short)t;

    // order-preserving float->uint; key = ord<<32 | (1023-t)  (desc val, asc idx)
    unsigned int bits = __float_as_uint(v);
    unsigned int ord  = (bits & 0x80000000u) ? ~bits : (bits | 0x80000000u);
    unsigned long long mykey = ((unsigned long long)ord << 32) | (unsigned int)(1023 - t);

    hist_add(hist1, (int)(ord >> 24), true, lane);
    __syncthreads();

    if (t < 32) {
        int T1, cA;
        find_thresh(hist1, KSEL, lane, T1, cA);
        if (lane == 0) { sT1 = T1; sneed2 = KSEL - cA; }
    }
    __syncthreads();

    const int T1 = sT1;
    hist_add(hist2, (int)((ord >> 16) & 0xFFu), (int)(ord >> 24) == T1, lane);
    __syncthreads();

    if (t < 32) {
        int T2, cA2;
        find_thresh(hist2, sneed2, lane, T2, cA2);
        if (lane == 0) sT2 = T2;
    }
    __syncthreads();

    const int T2 = sT2;
    {
        int b1 = (int)(ord >> 24);
        bool cand = (b1 > T1) || (b1 == T1 && (int)((ord >> 16) & 0xFFu) >= T2);
        if (cand) {
            unsigned int pos = atomicAdd(&ccnt, 1u);
            candkey[pos & 255u] = mykey;   // nc << 256 by construction
        }
    }
    __syncthreads();

    // exact rank among candidates == exact global rank (desc value, asc index)
    const int nc = (int)ccnt;
    if (t < nc) {
        unsigned long long my = candkey[t];
        int rank = 0;
        for (int j = 0; j < nc; ++j) rank += (candkey[j] > my);
        if (rank < KSEL) {
            int idx = 1023 - (int)(my & 0xFFFFFFFFu);
            selflag[idx] = 1;
            int xc = idx & 31, yc = idx >> 5;
            xc = max(xc, 1); yc = max(yc, 1);
            out[r * PTOT + rank] = (float)xc;
            out[NROWS * PTOT + r * PTOT + rank] = (float)yc;
        }
    }
    __syncthreads();

    // rank among unselected (ascending pixel index == stable argsort of mask)
    int alive = selflag[t] ? 0 : 1;
    unsigned int ballot = __ballot_sync(0xffffffffu, alive);
    int prefix_in_warp = __popc(ballot & ((1u << lane) - 1u));
    if (lane == 0) wtot[wrp] = __popc(ballot);
    __syncthreads();
    int wbase = 0;
    for (int i = 0; i < wrp; ++i) wbase += wtot[i];
    int rank = wbase + prefix_in_warp;

    if (alive) {
        int s = slot_of_rank[rank];
        if (s >= 0) {
            int xc = t & 31, yc = t >> 5;
            xc = max(xc, 1); yc = max(yc, 1);
            out[r * PTOT + KSEL + s] = (float)xc;
            out[NROWS * PTOT + r * PTOT + KSEL + s] = (float)yc;
        }
    }
}

// ---------------------------------------------------------------------------
// Host: replicate jax.random.permutation(jax.random.key(42), 1004)[:76]
// (threefry2x32, partitionable: foldlike split + xor random_bits)
// ---------------------------------------------------------------------------
static inline uint32_t rotl32(uint32_t v, int d) { return (v << d) | (v >> (32 - d)); }

static void threefry2x32_host(uint32_t k0, uint32_t k1, uint32_t c0, uint32_t c1,
                              uint32_t* o0, uint32_t* o1)
{
    uint32_t ks[3] = { k0, k1, k0 ^ k1 ^ 0x1BD11BDAu };
    static const int rot[2][4] = { {13, 15, 26, 6}, {17, 29, 16, 24} };
    uint32_t x0 = c0 + ks[0], x1 = c1 + ks[1];
    for (int g = 0; g < 5; ++g) {
        const int* rr = rot[g & 1];
        for (int i = 0; i < 4; ++i) {
            x0 += x1; x1 = rotl32(x1, rr[i]); x1 ^= x0;
        }
        x0 += ks[(g + 1) % 3];
        x1 += ks[(g + 2) % 3] + (uint32_t)(g + 1);
    }
    *o0 = x0; *o1 = x1;
}

static void compute_perm(int* perm76)
{
    uint32_t s0, s1;
    threefry2x32_host(0u, 42u, 0u, 1u, &s0, &s1);   // foldlike split of key(42)

    static uint32_t keys[NUNSEL];
    static int idx[NUNSEL];
    for (int i = 0; i < NUNSEL; ++i) {
        uint32_t o0, o1;
        threefry2x32_host(s0, s1, 0u, (uint32_t)i, &o0, &o1);
        keys[i] = o0 ^ o1;                           // partitionable random_bits
        idx[i] = i;
    }
    std::stable_sort(idx, idx + NUNSEL,
                     [](int a, int b) { return keys[a] < keys[b]; });
    for (int j = 0; j < NREM; ++j) perm76[j] = idx[j];
}

extern "C" void kernel_launch(void* const* d_in, const int* in_sizes, int n_in,
                              void* d_out, int out_size)
{
    const float* feat = (const float*)d_in[0];   // (8,16,384,32,32)
    const float* dw_w = (const float*)d_in[1];   // (384,1,3,3)
    // d_in[2] = dw_b (constant shift, irrelevant to ranking)
    const float* pw_w = (const float*)d_in[3];   // (1,384,1,1)
    // d_in[4] = pw_b (constant shift, irrelevant)

    Perm76 perm;
    compute_perm(perm.v);   // deterministic, host-side, capture-time only

    dim3 grid(NG, NROWS);
    conv_kernel<<<grid, 256>>>(feat, dw_w, pw_w);
    topk_kernel<<<NROWS, 1024>>>((float*)d_out, perm);
}

// round 14
// speedup vs baseline: 1.1499x; 1.0626x over previous
#include <cuda_runtime.h>
#include <cstdint>
#include <algorithm>

// Problem constants
#define NROWS   16          // only b=0 rows matter for the output
#define CTOT    384
#define NG      16          // channel groups
#define CPG     24          // channels per group (384/16)
#define HW      1024        // 32*32
#define KSEL    20
#define PTOT    96
#define NREM    76          // P - K
#define NUNSEL  1004        // 1024 - 20

struct Perm76 { int v[NREM]; };

// per-group score partials: [group][row][pixel] (1 MB, every slot written once)
__device__ float g_partial[NG][NROWS][HW];

// ---------------------------------------------------------------------------
// Kernel 1: tap-decomposed fused dw3x3*pw1x1 partial score (R11/R12 proven)
// ---------------------------------------------------------------------------
__global__ void __launch_bounds__(256) conv_kernel(
    const float* __restrict__ feat,
    const float* __restrict__ dw_w,
    const float* __restrict__ pw_w)
{
    const int grp = blockIdx.x;     // 0..15
    const int row = blockIdx.y;     // 0..15
    const int t   = threadIdx.x;    // 0..255
    const int p0  = t * 4;
    const int x4  = p0 & 31;
    const int y   = p0 >> 5;

    __shared__ float P[9][34 * 34];              // zero-padded tap planes (41.6 KB)
    __shared__ unsigned long long wp[CPG][9];    // packed (w,w) fused weights

    for (int i = t; i < 9 * 34 * 34; i += 256) (&P[0][0])[i] = 0.f;
    for (int i = t; i < CPG * 9; i += 256) {
        int ci = i / 9, k = i % 9, c = grp * CPG + ci;
        float w = pw_w[c] * dw_w[c * 9 + k];
        unsigned int u = __float_as_uint(w);
        wp[ci][k] = ((unsigned long long)u << 32) | (unsigned long long)u;
    }
    __syncthreads();

    const ulonglong2* base = reinterpret_cast<const ulonglong2*>(
        feat + ((size_t)row * CTOT + (size_t)grp * CPG) * HW) + t;

    unsigned long long accA[9], accB[9];
    #pragma unroll
    for (int k = 0; k < 9; ++k) { accA[k] = 0ull; accB[k] = 0ull; }

    #pragma unroll 8
    for (int c = 0; c < CPG; ++c) {
        ulonglong2 f = base[c * 256];            // 4 pixels (2x f32x2)
        #pragma unroll
        for (int k = 0; k < 9; ++k) {
            unsigned long long w = wp[c][k];
            asm("fma.rn.f32x2 %0, %1, %2, %0;" : "+l"(accA[k]) : "l"(f.x), "l"(w));
            asm("fma.rn.f32x2 %0, %1, %2, %0;" : "+l"(accB[k]) : "l"(f.y), "l"(w));
        }
    }

    // write tap planes (interior of padded 34x34)
    #pragma unroll
    for (int k = 0; k < 9; ++k) {
        float* pr = &P[k][(y + 1) * 34 + (x4 + 1)];
        pr[0] = __uint_as_float((unsigned int)(accA[k]));
        pr[1] = __uint_as_float((unsigned int)(accA[k] >> 32));
        pr[2] = __uint_as_float((unsigned int)(accB[k]));
        pr[3] = __uint_as_float((unsigned int)(accB[k] >> 32));
    }
    __syncthreads();

    // 9-tap gather: score(y,x) = sum_{ky,kx} P[ky*3+kx][(y+ky)*34 + (x+kx)]
    float s0 = 0.f, s1 = 0.f, s2 = 0.f, s3 = 0.f;
    #pragma unroll
    for (int ky = 0; ky < 3; ++ky)
        #pragma unroll
        for (int kx = 0; kx < 3; ++kx) {
            const float* pr = &P[ky * 3 + kx][(y + ky) * 34 + x4 + kx];
            s0 += pr[0]; s1 += pr[1]; s2 += pr[2]; s3 += pr[3];
        }

    __stcg(reinterpret_cast<float4*>(&g_partial[grp][row][p0]),
           make_float4(s0, s1, s2, s3));
}

// ---------------------------------------------------------------------------
// Kernel 2: per-row two-level radix top-20 (R7 structure, plain smem atomics,
// partial-sum loads issued before smem init)
// out layout: x_out[16][96] then y_out[16][96], FLOAT32
// ---------------------------------------------------------------------------
// find max bucket T with suffix count >= need; also count strictly above T.
// warp0 only; all lanes return identical T / cntAbove.
__device__ __forceinline__ void find_thresh(const unsigned int* hist, int need, int lane,
                                            int& T, int& cntAbove)
{
    const int base = lane * 8;
    unsigned int h[8], ls[8];
    #pragma unroll
    for (int j = 0; j < 8; ++j) h[j] = hist[base + j];
    ls[7] = h[7];
    #pragma unroll
    for (int j = 6; j >= 0; --j) ls[j] = ls[j + 1] + h[j];
    unsigned int tot = ls[0], s = tot;
    #pragma unroll
    for (int off = 1; off < 32; off <<= 1) {
        unsigned int o = __shfl_down_sync(0xffffffffu, s, off);
        if (lane + off < 32) s += o;
    }
    unsigned int hi = s - tot;          // totals of lanes strictly above this lane
    int best = -1;
    #pragma unroll
    for (int j = 7; j >= 0; --j)
        if (best < 0 && hi + ls[j] >= (unsigned int)need) best = base + j;
    #pragma unroll
    for (int off = 16; off; off >>= 1)
        best = max(best, __shfl_down_sync(0xffffffffu, best, off));
    best = __shfl_sync(0xffffffffu, best, 0);
    T = best;
    unsigned int c = 0;
    if (base > T)          c = tot;
    else if (base + 7 > T) c = ls[T - base + 1];
    #pragma unroll
    for (int off = 16; off; off >>= 1)
        c += __shfl_xor_sync(0xffffffffu, c, off);
    cntAbove = (int)c;
}

__global__ void __launch_bounds__(1024) topk_kernel(float* __restrict__ out, Perm76 perm)
{
    const int r = blockIdx.x;     // 0..15
    const int t = threadIdx.x;    // 0..1023 == pixel index
    const int lane = t & 31, wrp = t >> 5;

    __shared__ unsigned int        hist1[256];
    __shared__ unsigned int        hist2[256];
    __shared__ unsigned long long  candkey[256];
    __shared__ unsigned char       selflag[1024];
    __shared__ short               slot_of_rank[NUNSEL];
    __shared__ int                 wtot[32];
    __shared__ unsigned int        ccnt;
    __shared__ int                 sT1, sT2, sneed2;

    // issue the 16 independent partial-sum loads immediately (latency covered)
    float v = 0.f;
    #pragma unroll
    for (int g = 0; g < NG; ++g) v += __ldcg(&g_partial[g][r][t]);

    if (t < 256) { hist1[t] = 0u; hist2[t] = 0u; }
    selflag[t] = 0;
    if (t == 0) ccnt = 0u;
    for (int i = t; i < NUNSEL; i += 1024) slot_of_rank[i] = -1;
    __syncthreads();
    if (t < NREM) slot_of_rank[perm.v[t]] = (short)t;

    // order-preserving float->uint; key = ord<<32 | (1023-t)  (desc val, asc idx)
    unsigned int bits = __float_as_uint(v);
    unsigned int ord  = (bits & 0x80000000u) ? ~bits : (bits | 0x80000000u);
    unsigned long long mykey = ((unsigned long long)ord << 32) | (unsigned int)(1023 - t);

    atomicAdd(&hist1[ord >> 24], 1u);
    __syncthreads();

    if (t < 32) {
        int T1, cA;
        find_thresh(hist1, KSEL, lane, T1, cA);
        if (lane == 0) { sT1 = T1; sneed2 = KSEL - cA; }
    }
    __syncthreads();

    const int T1 = sT1;
    if ((int)(ord >> 24) == T1)
        atomicAdd(&hist2[(ord >> 16) & 0xFFu], 1u);
    __syncthreads();

    if (t < 32) {
        int T2, cA2;
        find_thresh(hist2, sneed2, lane, T2, cA2);
        if (lane == 0) sT2 = T2;
    }
    __syncthreads();

    const int T2 = sT2;
    {
        int b1 = (int)(ord >> 24);
        bool cand = (b1 > T1) || (b1 == T1 && (int)((ord >> 16) & 0xFFu) >= T2);
        if (cand) {
            unsigned int pos = atomicAdd(&ccnt, 1u);
            candkey[pos & 255u] = mykey;   // nc << 256 by construction
        }
    }
    __syncthreads();

    // exact rank among candidates == exact global rank (desc value, asc index)
    const int nc = (int)ccnt;
    if (t < nc) {
        unsigned long long my = candkey[t];
        int rank = 0;
        for (int j = 0; j < nc; ++j) rank += (candkey[j] > my);
        if (rank < KSEL) {
            int idx = 1023 - (int)(my & 0xFFFFFFFFu);
            selflag[idx] = 1;
            int xc = idx & 31, yc = idx >> 5;
            xc = max(xc, 1); yc = max(yc, 1);
            out[r * PTOT + rank] = (float)xc;
            out[NROWS * PTOT + r * PTOT + rank] = (float)yc;
        }
    }
    __syncthreads();

    // rank among unselected (ascending pixel index == stable argsort of mask)
    int alive = selflag[t] ? 0 : 1;
    unsigned int ballot = __ballot_sync(0xffffffffu, alive);
    int prefix_in_warp = __popc(ballot & ((1u << lane) - 1u));
    if (lane == 0) wtot[wrp] = __popc(ballot);
    __syncthreads();
    int wbase = 0;
    for (int i = 0; i < wrp; ++i) wbase += wtot[i];
    int rank = wbase + prefix_in_warp;

    if (alive) {
        int s = slot_of_rank[rank];
        if (s >= 0) {
            int xc = t & 31, yc = t >> 5;
            xc = max(xc, 1); yc = max(yc, 1);
            out[r * PTOT + KSEL + s] = (float)xc;
            out[NROWS * PTOT + r * PTOT + KSEL + s] = (float)yc;
        }
    }
}

// ---------------------------------------------------------------------------
// Host: replicate jax.random.permutation(jax.random.key(42), 1004)[:76]
// (threefry2x32, partitionable: foldlike split + xor random_bits)
// ---------------------------------------------------------------------------
static inline uint32_t rotl32(uint32_t v, int d) { return (v << d) | (v >> (32 - d)); }

static void threefry2x32_host(uint32_t k0, uint32_t k1, uint32_t c0, uint32_t c1,
                              uint32_t* o0, uint32_t* o1)
{
    uint32_t ks[3] = { k0, k1, k0 ^ k1 ^ 0x1BD11BDAu };
    static const int rot[2][4] = { {13, 15, 26, 6}, {17, 29, 16, 24} };
    uint32_t x0 = c0 + ks[0], x1 = c1 + ks[1];
    for (int g = 0; g < 5; ++g) {
        const int* rr = rot[g & 1];
        for (int i = 0; i < 4; ++i) {
            x0 += x1; x1 = rotl32(x1, rr[i]); x1 ^= x0;
        }
        x0 += ks[(g + 1) % 3];
        x1 += ks[(g + 2) % 3] + (uint32_t)(g + 1);
    }
    *o0 = x0; *o1 = x1;
}

static void compute_perm(int* perm76)
{
    uint32_t s0, s1;
    threefry2x32_host(0u, 42u, 0u, 1u, &s0, &s1);   // foldlike split of key(42)

    static uint32_t keys[NUNSEL];
    static int idx[NUNSEL];
    for (int i = 0; i < NUNSEL; ++i) {
        uint32_t o0, o1;
        threefry2x32_host(s0, s1, 0u, (uint32_t)i, &o0, &o1);
        keys[i] = o0 ^ o1;                           // partitionable random_bits
        idx[i] = i;
    }
    std::stable_sort(idx, idx + NUNSEL,
                     [](int a, int b) { return keys[a] < keys[b]; });
    for (int j = 0; j < NREM; ++j) perm76[j] = idx[j];
}

extern "C" void kernel_launch(void* const* d_in, const int* in_sizes, int n_in,
                              void* d_out, int out_size)
{
    const float* feat = (const float*)d_in[0];   // (8,16,384,32,32)
    const float* dw_w = (const float*)d_in[1];   // (384,1,3,3)
    // d_in[2] = dw_b (constant shift, irrelevant to ranking)
    const float* pw_w = (const float*)d_in[3];   // (1,384,1,1)
    // d_in[4] = pw_b (constant shift, irrelevant)

    Perm76 perm;
    compute_perm(perm.v);   // deterministic, host-side, capture-time only

    dim3 grid(NG, NROWS);
    conv_kernel<<<grid, 256>>>(feat, dw_w, pw_w);
    topk_kernel<<<NROWS, 1024>>>((float*)d_out, perm);
}